// round 15
// baseline (speedup 1.0000x reference)
#include <cuda_runtime.h>
#include <cuda_bf16.h>
#include <cuda_fp16.h>
#include <mma.h>
#include <math.h>

// Problem dims
#define BB 8
#define TT 256
#define UU 64
#define VV 1024
#define JJ 512      // joint dim (K of second GEMM)
#define EE 256      // enc/pred dim (K of first GEMM)

#define LOG2E 1.4426950408889634f
#define LN2   0.6931471805599453f

// Scratch (static __device__ arrays: allowed; no runtime alloc)
__device__ __half g_ep[BB * TT * JJ];           // 2 MB: enc proj + b1 (fp16)
__device__ __half g_dp[BB * UU * JJ];           // 0.5 MB: dec proj (fp16)
__device__ __half g_w2h[VV * JJ];               // 1 MB: W2 * log2e (fp16)
__device__ float  g_b2s[VV];                    // b2 * log2e (fp32)

__device__ __forceinline__ __half2 h2_tanh_approx(__half2 x) {
    unsigned r, a = *(unsigned*)&x;
    asm("tanh.approx.f16x2 %0, %1;" : "=r"(r) : "r"(a));
    return *(__half2*)&r;
}
__device__ __forceinline__ __half2 h2_ex2_approx(__half2 x) {
    unsigned r, a = *(unsigned*)&x;
    asm("ex2.approx.f16x2 %0, %1;" : "=r"(r) : "r"(a));
    return *(__half2*)&r;
}

// ---------------------------------------------------------------------------
// Kernel P: fused prep.
//   part A (grid-stride): W2 -> fp16 * log2e; b2 -> fp32 * log2e
//   part B: projection GEMMs -> g_ep (fp16, +b1), g_dp (fp16)
// grid = 320 CTAs x 256 threads; proj block = (r0, j0) 64x64 tile.
// ---------------------------------------------------------------------------
__global__ void prep_kernel(const float* __restrict__ enc,
                            const float* __restrict__ dec,
                            const float* __restrict__ W1,
                            const float* __restrict__ b1,
                            const float* __restrict__ W2,
                            const float* __restrict__ b2) {
    // ---- part A ----
    {
        int gt = blockIdx.x * blockDim.x + threadIdx.x;   // 0..81919
        for (int i = gt; i < VV * JJ; i += 320 * 256)
            g_w2h[i] = __float2half(W2[i] * LOG2E);
        if (gt < VV) g_b2s[gt] = b2[gt] * LOG2E;
    }

    // ---- part B: 64x64 fp32 GEMM tile ----
    __shared__ float As[32][68];   // [k][r]
    __shared__ float Bs[32][68];   // [k][j]
    const int tid = threadIdx.x;
    const int tx = tid & 15, ty = tid >> 4;   // 16x16
    const int j0 = (blockIdx.x & 7) * 64;     // 8 j-tiles
    const int r0 = (blockIdx.x >> 3) * 64;    // 40 r-tiles
    const bool is_ep = (r0 < BB * TT);
    const float* A = is_ep ? (enc + (size_t)r0 * EE)
                           : (dec + (size_t)(r0 - BB * TT) * EE);
    const int koff = is_ep ? 0 : EE;

    float c[4][4];
#pragma unroll
    for (int i = 0; i < 4; i++)
#pragma unroll
        for (int j = 0; j < 4; j++) c[i][j] = 0.f;

    for (int kb = 0; kb < EE; kb += 32) {
#pragma unroll
        for (int l = 0; l < 8; l++) {
            int e = tid + l * 256;
            int row = e >> 5, col = e & 31;
            As[col][row] = A[row * EE + kb + col];
            Bs[col][row] = W1[(size_t)(j0 + row) * JJ + koff + kb + col];
        }
        __syncthreads();
#pragma unroll
        for (int kk = 0; kk < 32; kk++) {
            float4 a = *(const float4*)&As[kk][ty * 4];
            float4 b = *(const float4*)&Bs[kk][tx * 4];
            c[0][0] += a.x * b.x; c[0][1] += a.x * b.y; c[0][2] += a.x * b.z; c[0][3] += a.x * b.w;
            c[1][0] += a.y * b.x; c[1][1] += a.y * b.y; c[1][2] += a.y * b.z; c[1][3] += a.y * b.w;
            c[2][0] += a.z * b.x; c[2][1] += a.z * b.y; c[2][2] += a.z * b.z; c[2][3] += a.z * b.w;
            c[3][0] += a.w * b.x; c[3][1] += a.w * b.y; c[3][2] += a.w * b.z; c[3][3] += a.w * b.w;
        }
        __syncthreads();
    }
#pragma unroll
    for (int i = 0; i < 4; i++) {
        int r = r0 + ty * 4 + i;
#pragma unroll
        for (int j = 0; j < 4; j++) {
            int jg = j0 + tx * 4 + j;
            float v = c[i][j];
            if (is_ep) g_ep[(size_t)r * JJ + jg] = __float2half(v + __ldg(&b1[jg]));
            else       g_dp[(size_t)(r - BB * TT) * JJ + jg] = __float2half(v);
        }
    }
}

// ---------------------------------------------------------------------------
// Kernel 2: fused joint. One CTA (512 threads) per (b,t).
//   h = tanh.approx.f16x2(ep+dp)                  (fp16 smem)
//   stored = h @ (W2*log2e)^T + b2*log2e          (wmma fp16, fp32 acc)
//   exp computed in the epilogue on the stored values (ex2.f16x2);
//   row sums in registers; out = (stored - log2(sum)) * ln2.
// 16 warps: wm = warp&3 (16 M-rows), wn = warp>>2 (32 N-cols), acc[2].
// ---------------------------------------------------------------------------
#define H_LD   520
#define ST_LD  136
#define TMP_LD 132
#define SM_H     (64 * H_LD * 2)           // 66560
#define SM_LOG   (64 * VV * 2)             // 131072
#define SM_UNION (128 * ST_LD * 2)         // 34816 (>= 64*132*4, >= 64*8*4+256)
#define SMEM_TOTAL (SM_H + SM_LOG + SM_UNION)   // 232448

using namespace nvcuda;

__global__ void __launch_bounds__(512, 1)
joint_kernel(float* __restrict__ out) {
    extern __shared__ char smem[];
    __half* h_s   = (__half*)smem;
    __half* log_s = (__half*)(smem + SM_H);       // logit * log2e, fp16
    char*   ub    = smem + SM_H + SM_LOG;
    __half* stage = (__half*)ub;                  // [128][ST_LD]
    float*  temp  = (float*)ub;                   // [64][TMP_LD]
    float*  part  = (float*)ub;                   // [64][8] after loop
    float*  lse_s = (float*)(ub + 2048);          // [64]

    const int tid = threadIdx.x;
    const int n = blockIdx.x;            // n = b*T + t
    const int b = n >> 8;                // T = 256

    // ---- Phase 1: h = tanh(ep + dp) -- fp16 HADD2 + MUFU.TANH ----
    const __half* ep  = g_ep + (size_t)n * JJ;
    const __half* dpb = g_dp + (size_t)b * UU * JJ;
#pragma unroll
    for (int i = tid; i < 64 * 64; i += 512) {    // 64 rows x 64 uint4-groups
        int u = i >> 6, g8 = (i & 63) << 3;
        uint4 ev = *(const uint4*)(ep + g8);
        uint4 dv = *(const uint4*)(dpb + (size_t)u * JJ + g8);
        const __half2* e2 = (const __half2*)&ev;
        const __half2* d2 = (const __half2*)&dv;
        uint4 hv;
        __half2* h2 = (__half2*)&hv;
        h2[0] = h2_tanh_approx(__hadd2(e2[0], d2[0]));
        h2[1] = h2_tanh_approx(__hadd2(e2[1], d2[1]));
        h2[2] = h2_tanh_approx(__hadd2(e2[2], d2[2]));
        h2[3] = h2_tanh_approx(__hadd2(e2[3], d2[3]));
        *(uint4*)(h_s + u * H_LD + g8) = hv;
    }
    __syncthreads();

    // ---- Phase 2: GEMM + epilogue(exp fused), N in 8 chunks of 128 ----
    const int warp = tid >> 5;
    const int wm = warp & 3;      // 16-row M slice
    const int wn = warp >> 2;     // 32-col N slice
    const int eu = tid >> 3;      // epilogue row (0..63)
    const int ec = (tid & 7) * 16;   // epilogue col offset within chunk
    float rowsum = 0.f;

    for (int nc = 0; nc < 8; nc++) {
        const int n0 = nc * 128;
        wmma::fragment<wmma::accumulator, 16, 16, 16, float> acc[2];
        wmma::fill_fragment(acc[0], 0.0f);
        wmma::fill_fragment(acc[1], 0.0f);

        // prefetch kb=0 W2 stage into registers (4 uint4 / thread)
        uint4 pre[4];
#pragma unroll
        for (int l = 0; l < 4; l++) {
            int e = tid + l * 512;
            int r = e >> 4, c8 = e & 15;
            pre[l] = *(const uint4*)(g_w2h + (size_t)(n0 + r) * JJ + c8 * 8);
        }

        for (int kb = 0; kb < 4; kb++) {
            __syncthreads();   // stage free
#pragma unroll
            for (int l = 0; l < 4; l++) {
                int e = tid + l * 512;
                int r = e >> 4, c8 = e & 15;
                *(uint4*)&stage[r * ST_LD + c8 * 8] = pre[l];
            }
            __syncthreads();
            if (kb < 3) {      // overlap next stage LDG with this kb's MMAs
#pragma unroll
                for (int l = 0; l < 4; l++) {
                    int e = tid + l * 512;
                    int r = e >> 4, c8 = e & 15;
                    pre[l] = *(const uint4*)(g_w2h + (size_t)(n0 + r) * JJ
                                             + (kb + 1) * 128 + c8 * 8);
                }
            }
#pragma unroll
            for (int ks = 0; ks < 8; ks++) {
                const int k = kb * 128 + ks * 16;
                const int krel = ks * 16;
                wmma::fragment<wmma::matrix_a, 16, 16, 16, __half, wmma::row_major> af;
                wmma::fragment<wmma::matrix_b, 16, 16, 16, __half, wmma::col_major> bf[2];
                wmma::load_matrix_sync(af, h_s + (wm * 16) * H_LD + k, H_LD);
                wmma::load_matrix_sync(bf[0], stage + (wn * 32) * ST_LD + krel, ST_LD);
                wmma::load_matrix_sync(bf[1], stage + (wn * 32 + 16) * ST_LD + krel, ST_LD);
                wmma::mma_sync(acc[0], af, bf[0], acc[0]);
                wmma::mma_sync(acc[1], af, bf[1], acc[1]);
            }
        }
        __syncthreads();   // MMA done; stage -> temp reuse
        wmma::store_matrix_sync(temp + (wm * 16) * TMP_LD + wn * 32,
                                acc[0], TMP_LD, wmma::mem_row_major);
        wmma::store_matrix_sync(temp + (wm * 16) * TMP_LD + wn * 32 + 16,
                                acc[1], TMP_LD, wmma::mem_row_major);
        __syncthreads();

        // epilogue: thread owns (row eu, cols ec..ec+16) of this chunk.
        // add b2s, store fp16 to log_s, and exp-accumulate in one pass.
        {
            const float* trow = temp + eu * TMP_LD + ec;
            const float* brow = g_b2s + n0 + ec;
            __half* lrow = log_s + (size_t)eu * VV + n0 + ec;
            uint4 ov4[2];
            __half2* ov = (__half2*)ov4;
#pragma unroll
            for (int q = 0; q < 4; q++) {
                float4 t  = *(const float4*)(trow + 4 * q);
                float4 bb = __ldg((const float4*)(brow + 4 * q));
                ov[2 * q + 0] = __floats2half2_rn(t.x + bb.x, t.y + bb.y);
                ov[2 * q + 1] = __floats2half2_rn(t.z + bb.z, t.w + bb.w);
            }
            *(uint4*)lrow = ov4[0];
            *((uint4*)lrow + 1) = ov4[1];
            // exp on the exact stored fp16 values (consistent with phase 4)
            __half2 s0 = __hadd2(__hadd2(h2_ex2_approx(ov[0]), h2_ex2_approx(ov[1])),
                                 __hadd2(h2_ex2_approx(ov[2]), h2_ex2_approx(ov[3])));
            __half2 s1 = __hadd2(__hadd2(h2_ex2_approx(ov[4]), h2_ex2_approx(ov[5])),
                                 __hadd2(h2_ex2_approx(ov[6]), h2_ex2_approx(ov[7])));
            float2 f0 = __half22float2(s0);
            float2 f1 = __half22float2(s1);
            rowsum += (f0.x + f0.y) + (f1.x + f1.y);
        }
    }

    // ---- reduce row sums: 8 threads per row -> lse ----
    __syncthreads();                       // temp dead; union -> part/lse
    part[eu * 8 + (tid & 7)] = rowsum;
    __syncthreads();
    if (tid < 64) {
        const float* p = part + tid * 8;
        float s = ((p[0] + p[1]) + (p[2] + p[3])) + ((p[4] + p[5]) + (p[6] + p[7]));
        lse_s[tid] = __log2f(s);           // log2 of sum of 2^stored
    }
    __syncthreads();

    // ---- Phase 4: out = (stored - log2sum) * ln2, coalesced float4 ----
    float* ob = out + (size_t)n * (UU * VV);
#pragma unroll
    for (int i2 = tid; i2 < 64 * 256; i2 += 512) {
        int u = i2 >> 8, c = (i2 & 255) << 2;
        float nl = -lse_s[u] * LN2;
        const __half2* lp = (const __half2*)(log_s + (size_t)u * VV + c);
        float2 f0 = __half22float2(lp[0]);
        float2 f1 = __half22float2(lp[1]);
        float4 o;
        o.x = fmaf(f0.x, LN2, nl); o.y = fmaf(f0.y, LN2, nl);
        o.z = fmaf(f1.x, LN2, nl); o.w = fmaf(f1.y, LN2, nl);
        *(float4*)(ob + (size_t)u * VV + c) = o;
    }
}

// ---------------------------------------------------------------------------
extern "C" void kernel_launch(void* const* d_in, const int* in_sizes, int n_in,
                              void* d_out, int out_size) {
    const float* enc = (const float*)d_in[0];   // (8,256,256)
    const float* dec = (const float*)d_in[1];   // (8,64,256)
    const float* W1  = (const float*)d_in[2];   // (512,512)
    const float* b1  = (const float*)d_in[3];   // (512,)
    const float* W2  = (const float*)d_in[4];   // (1024,512)
    const float* b2  = (const float*)d_in[5];   // (1024,)
    float* out = (float*)d_out;                 // (8,256,64,1024) fp32

    prep_kernel<<<320, 256>>>(enc, dec, W1, b1, W2, b2);

    cudaFuncSetAttribute(joint_kernel,
                         cudaFuncAttributeMaxDynamicSharedMemorySize, SMEM_TOTAL);
    joint_kernel<<<BB * TT, 512, SMEM_TOTAL>>>(out);
}